// round 12
// baseline (speedup 1.0000x reference)
#include <cuda_runtime.h>

typedef unsigned long long u64;

// ---------- packed f32x2 helpers (sm_103a) ----------
static __device__ __forceinline__ u64 pack2(float x, float y) {
    u64 r; asm("mov.b64 %0, {%1, %2};" : "=l"(r) : "f"(x), "f"(y)); return r;
}
static __device__ __forceinline__ float2 unpack2(u64 v) {
    float2 r; asm("mov.b64 {%0, %1}, %2;" : "=f"(r.x), "=f"(r.y) : "l"(v)); return r;
}
static __device__ __forceinline__ void ffma2(u64& d, u64 a, u64 b) {
    asm("fma.rn.f32x2 %0, %1, %2, %0;" : "+l"(d) : "l"(a), "l"(b));
}
static __device__ __forceinline__ u64 fadd2(u64 a, u64 b) {
    u64 d; asm("add.rn.f32x2 %0, %1, %2;" : "=l"(d) : "l"(a), "l"(b)); return d;
}

// ---------- problem constants ----------
// B=8, H=W=256, C=192, WS=8, SHIFT=4, 6 heads x 32 dim
// tokens laid out (b, window, pixel): 8 * 1024 * 64 = 524288
#define NTOK 524288

// scratch (static __device__ arrays: allocation-guard-safe)
__device__ float g_qkv[(size_t)NTOK * 576];   // [token][576] : q|k|v per head
__device__ float g_att[(size_t)NTOK * 192];   // attention output per token

// Map token id -> source/destination pixel row in the (B,256,256) image.
// roll(-4) on input and roll(+4) on output give the identical index.
static __device__ __forceinline__ int src_row(int t) {
    int b   = t >> 16;
    int win = (t >> 6) & 1023;
    int p   = t & 63;
    int h = (((win >> 5) << 3) + (p >> 3) + 4) & 255;
    int w = (((win & 31) << 3) + (p & 7)  + 4) & 255;
    return (b << 16) | (h << 8) | w;
}

// =====================================================================
// Kernel 1: fused roll + window partition + QKV GEMM
// M = 524288 tokens, K = 192, N = 576.  CTA tile 128x64, 128 threads,
// 8x8 per thread via packed f32x2 FMA.
// =====================================================================
__global__ void __launch_bounds__(128) k_qkv(const float* __restrict__ x,
                                             const float* __restrict__ wq,
                                             const float* __restrict__ bq)
{
    __shared__ float As[16][128];
    __shared__ float Bs[16][64];
    const int tid = threadIdx.x;
    const int nb  = blockIdx.x << 6;   // 0..512
    const int t0  = blockIdx.y << 7;   // token tile base
    const int tm  = tid >> 3, tn = tid & 7;

    const float* arow = x + (size_t)src_row(t0 + tid) * 192;
    const int k0 = tid >> 4;           // 0..7
    const int j0 = (tid & 15) << 2;    // 0..60
    const int k1 = k0 + 8;

    u64 acc[8][4];
    #pragma unroll
    for (int i = 0; i < 8; ++i)
        #pragma unroll
        for (int j = 0; j < 4; ++j) acc[i][j] = 0ull;

    for (int kt = 0; kt < 192; kt += 16) {
        float4 a0 = *(const float4*)(arow + kt + 0);
        float4 a1 = *(const float4*)(arow + kt + 4);
        float4 a2 = *(const float4*)(arow + kt + 8);
        float4 a3 = *(const float4*)(arow + kt + 12);
        float4 b0 = *(const float4*)(wq + (size_t)(kt + k0) * 576 + nb + j0);
        float4 b1 = *(const float4*)(wq + (size_t)(kt + k1) * 576 + nb + j0);
        __syncthreads();
        As[0][tid] = a0.x;  As[1][tid] = a0.y;  As[2][tid] = a0.z;  As[3][tid] = a0.w;
        As[4][tid] = a1.x;  As[5][tid] = a1.y;  As[6][tid] = a1.z;  As[7][tid] = a1.w;
        As[8][tid] = a2.x;  As[9][tid] = a2.y;  As[10][tid] = a2.z; As[11][tid] = a2.w;
        As[12][tid] = a3.x; As[13][tid] = a3.y; As[14][tid] = a3.z; As[15][tid] = a3.w;
        *(float4*)&Bs[k0][j0] = b0;
        *(float4*)&Bs[k1][j0] = b1;
        __syncthreads();
        #pragma unroll
        for (int k = 0; k < 16; ++k) {
            float4 x0 = *(const float4*)&As[k][tm << 3];
            float4 x1 = *(const float4*)&As[k][(tm << 3) + 4];
            ulonglong2 u0 = *(const ulonglong2*)&Bs[k][tn << 3];
            ulonglong2 u1 = *(const ulonglong2*)&Bs[k][(tn << 3) + 4];
            u64 bb0 = u0.x, bb1 = u0.y, bb2 = u1.x, bb3 = u1.y;
            u64 aa[8];
            aa[0] = pack2(x0.x, x0.x); aa[1] = pack2(x0.y, x0.y);
            aa[2] = pack2(x0.z, x0.z); aa[3] = pack2(x0.w, x0.w);
            aa[4] = pack2(x1.x, x1.x); aa[5] = pack2(x1.y, x1.y);
            aa[6] = pack2(x1.z, x1.z); aa[7] = pack2(x1.w, x1.w);
            #pragma unroll
            for (int i = 0; i < 8; ++i) {
                ffma2(acc[i][0], aa[i], bb0);
                ffma2(acc[i][1], aa[i], bb1);
                ffma2(acc[i][2], aa[i], bb2);
                ffma2(acc[i][3], aa[i], bb3);
            }
        }
    }

    u64 bias2[4];
    #pragma unroll
    for (int j = 0; j < 4; ++j)
        bias2[j] = pack2(bq[nb + (tn << 3) + 2 * j], bq[nb + (tn << 3) + 2 * j + 1]);
    #pragma unroll
    for (int i = 0; i < 8; ++i) {
        int t = t0 + (tm << 3) + i;
        u64* dst = (u64*)(g_qkv + (size_t)t * 576 + nb + (tn << 3));
        #pragma unroll
        for (int j = 0; j < 4; ++j) dst[j] = fadd2(acc[i][j], bias2[j]);
    }
}

// =====================================================================
// Kernel 2: windowed attention. One CTA per (window, head), 64 threads.
// Thread p owns query pixel p: QK^T row, bias+mask, softmax, PV row.
// =====================================================================
__global__ void __launch_bounds__(64) k_attn(const float* __restrict__ rel_pos)
{
    __shared__ u64 ks[64][16];
    __shared__ u64 vs[64][16];
    __shared__ float bs[225];

    const int p    = threadIdx.x;
    const int wid  = blockIdx.x;          // b*1024 + window
    const int head = blockIdx.y;
    const int wh = (wid >> 5) & 31, wwc = wid & 31;
    const size_t tb = (size_t)wid << 6;
    const float* base = g_qkv + tb * 576;

    // cooperative K/V tile load (64 rows x 32 floats each)
    #pragma unroll
    for (int l = 0; l < 8; ++l) {
        int flat = (l << 6) + p;
        int row = flat >> 3, c4 = flat & 7;
        const float* kr = base + row * 576 + 192 + head * 32;
        const float* vr = base + row * 576 + 384 + head * 32;
        ((ulonglong2*)&ks[row][0])[c4] = ((const ulonglong2*)kr)[c4];
        ((ulonglong2*)&vs[row][0])[c4] = ((const ulonglong2*)vr)[c4];
    }
    for (int i = p; i < 225; i += 64) bs[i] = rel_pos[head * 225 + i];

    u64 q2[16];
    {
        const ulonglong2* qp = (const ulonglong2*)(base + p * 576 + head * 32);
        #pragma unroll
        for (int c = 0; c < 8; ++c) { ulonglong2 t = qp[c]; q2[2*c] = t.x; q2[2*c+1] = t.y; }
    }
    __syncthreads();

    const int pi = p >> 3, pj = p & 7;
    const bool lastH = (wh == 31), lastW = (wwc == 31);

    float s[64];
    #pragma unroll
    for (int q = 0; q < 64; ++q) {
        u64 a = 0ull;
        #pragma unroll
        for (int c = 0; c < 16; ++c) ffma2(a, q2[c], ks[q][c]);
        float2 f = unpack2(a);
        int qi = q >> 3, qj = q & 7;
        float v = (f.x + f.y) * 0.17677669529663687f
                + bs[(pi - qi + 7) * 15 + (pj - qj + 7)];
        bool m = (lastH && ((pi < 4) != (qi < 4))) ||
                 (lastW && ((pj < 4) != (qj < 4)));
        s[q] = m ? -1e30f : v;
    }

    float mx = -1e30f;
    #pragma unroll
    for (int q = 0; q < 64; ++q) mx = fmaxf(mx, s[q]);
    float sum = 0.f;
    #pragma unroll
    for (int q = 0; q < 64; ++q) { float e = __expf(s[q] - mx); s[q] = e; sum += e; }
    const float inv = 1.f / sum;

    u64 o[16];
    #pragma unroll
    for (int d = 0; d < 16; ++d) o[d] = 0ull;
    #pragma unroll
    for (int q = 0; q < 64; ++q) {
        float pr = s[q] * inv;
        u64 pd = pack2(pr, pr);
        #pragma unroll
        for (int d = 0; d < 16; ++d) ffma2(o[d], pd, vs[q][d]);
    }
    u64* op = (u64*)(g_att + (tb + p) * 192 + head * 32);
    #pragma unroll
    for (int d = 0; d < 16; ++d) op[d] = o[d];
}

// =====================================================================
// Kernel 3: output projection GEMM (524288 x 192 x 192) fused with the
// reverse-roll scatter into d_out.
// =====================================================================
__global__ void __launch_bounds__(128) k_out(const float* __restrict__ wo,
                                             const float* __restrict__ bo,
                                             float* __restrict__ out)
{
    __shared__ float As[16][128];
    __shared__ float Bs[16][64];
    const int tid = threadIdx.x;
    const int nb  = blockIdx.x << 6;   // 0..128
    const int t0  = blockIdx.y << 7;
    const int tm  = tid >> 3, tn = tid & 7;

    const float* arow = g_att + (size_t)(t0 + tid) * 192;
    const int k0 = tid >> 4;
    const int j0 = (tid & 15) << 2;
    const int k1 = k0 + 8;

    u64 acc[8][4];
    #pragma unroll
    for (int i = 0; i < 8; ++i)
        #pragma unroll
        for (int j = 0; j < 4; ++j) acc[i][j] = 0ull;

    for (int kt = 0; kt < 192; kt += 16) {
        float4 a0 = *(const float4*)(arow + kt + 0);
        float4 a1 = *(const float4*)(arow + kt + 4);
        float4 a2 = *(const float4*)(arow + kt + 8);
        float4 a3 = *(const float4*)(arow + kt + 12);
        float4 b0 = *(const float4*)(wo + (size_t)(kt + k0) * 192 + nb + j0);
        float4 b1 = *(const float4*)(wo + (size_t)(kt + k1) * 192 + nb + j0);
        __syncthreads();
        As[0][tid] = a0.x;  As[1][tid] = a0.y;  As[2][tid] = a0.z;  As[3][tid] = a0.w;
        As[4][tid] = a1.x;  As[5][tid] = a1.y;  As[6][tid] = a1.z;  As[7][tid] = a1.w;
        As[8][tid] = a2.x;  As[9][tid] = a2.y;  As[10][tid] = a2.z; As[11][tid] = a2.w;
        As[12][tid] = a3.x; As[13][tid] = a3.y; As[14][tid] = a3.z; As[15][tid] = a3.w;
        *(float4*)&Bs[k0][j0] = b0;
        *(float4*)&Bs[k1][j0] = b1;
        __syncthreads();
        #pragma unroll
        for (int k = 0; k < 16; ++k) {
            float4 x0 = *(const float4*)&As[k][tm << 3];
            float4 x1 = *(const float4*)&As[k][(tm << 3) + 4];
            ulonglong2 u0 = *(const ulonglong2*)&Bs[k][tn << 3];
            ulonglong2 u1 = *(const ulonglong2*)&Bs[k][(tn << 3) + 4];
            u64 bb0 = u0.x, bb1 = u0.y, bb2 = u1.x, bb3 = u1.y;
            u64 aa[8];
            aa[0] = pack2(x0.x, x0.x); aa[1] = pack2(x0.y, x0.y);
            aa[2] = pack2(x0.z, x0.z); aa[3] = pack2(x0.w, x0.w);
            aa[4] = pack2(x1.x, x1.x); aa[5] = pack2(x1.y, x1.y);
            aa[6] = pack2(x1.z, x1.z); aa[7] = pack2(x1.w, x1.w);
            #pragma unroll
            for (int i = 0; i < 8; ++i) {
                ffma2(acc[i][0], aa[i], bb0);
                ffma2(acc[i][1], aa[i], bb1);
                ffma2(acc[i][2], aa[i], bb2);
                ffma2(acc[i][3], aa[i], bb3);
            }
        }
    }

    u64 bias2[4];
    #pragma unroll
    for (int j = 0; j < 4; ++j)
        bias2[j] = pack2(bo[nb + (tn << 3) + 2 * j], bo[nb + (tn << 3) + 2 * j + 1]);
    #pragma unroll
    for (int i = 0; i < 8; ++i) {
        int t = t0 + (tm << 3) + i;
        u64* dst = (u64*)(out + (size_t)src_row(t) * 192 + nb + (tn << 3));
        #pragma unroll
        for (int j = 0; j < 4; ++j) dst[j] = fadd2(acc[i][j], bias2[j]);
    }
}

// =====================================================================
extern "C" void kernel_launch(void* const* d_in, const int* in_sizes, int n_in,
                              void* d_out, int out_size)
{
    const float* x  = (const float*)d_in[0];   // (8,256,256,192) f32
    const float* wq = (const float*)d_in[1];   // (192,576)
    const float* bq = (const float*)d_in[2];   // (576,)
    const float* rp = (const float*)d_in[3];   // (6,15,15)
    const float* wo = (const float*)d_in[4];   // (192,192)
    const float* bo = (const float*)d_in[5];   // (192,)
    float* out = (float*)d_out;                // (8,256,256,192) f32

    k_qkv <<<dim3(9, 4096), 128>>>(x, wq, bq);
    k_attn<<<dim3(8192, 6), 64>>>(rp);
    k_out <<<dim3(3, 4096), 128>>>(wo, bo, out);
}

// round 16
// speedup vs baseline: 1.8095x; 1.8095x over previous
#include <cuda_runtime.h>
#include <cuda_bf16.h>

typedef unsigned long long u64;
typedef unsigned int u32;

// ===================== helpers =====================
static __device__ __forceinline__ u64 pack2(float x, float y) {
    u64 r; asm("mov.b64 %0, {%1, %2};" : "=l"(r) : "f"(x), "f"(y)); return r;
}
static __device__ __forceinline__ float2 unpack2(u64 v) {
    float2 r; asm("mov.b64 {%0, %1}, %2;" : "=f"(r.x), "=f"(r.y) : "l"(v)); return r;
}
static __device__ __forceinline__ void ffma2(u64& d, u64 a, u64 b) {
    asm("fma.rn.f32x2 %0, %1, %2, %0;" : "+l"(d) : "l"(a), "l"(b));
}
static __device__ __forceinline__ u32 smem_u32(const void* p) {
    u32 a; asm("{ .reg .u64 t; cvta.to.shared.u64 t, %1; cvt.u32.u64 %0, t; }" : "=r"(a) : "l"(p));
    return a;
}
// pack two floats to bf16x2 (a -> low half / lower address, b -> high half)
static __device__ __forceinline__ u32 bfp(float a, float b) {
    u32 r; asm("cvt.rn.bf16x2.f32 %0, %1, %2;" : "=r"(r) : "f"(b), "f"(a)); return r;
}
static __device__ __forceinline__ void bsplit(float v, float& hf, float& lf) {
    __nv_bfloat16 h = __float2bfloat16(v);
    hf = __bfloat162float(h);
    lf = v - hf;
}

// ===================== base-ISA tensor ops (no tcgen05!) =====================
#define LDSM4(r, addr) \
    asm volatile("ldmatrix.sync.aligned.m8n8.x4.shared.b16 {%0,%1,%2,%3}, [%4];" \
        : "=r"((r)[0]), "=r"((r)[1]), "=r"((r)[2]), "=r"((r)[3]) : "r"(addr))

static __device__ __forceinline__ void mma16816(float* d, const u32* a, u32 b0, u32 b1) {
    asm volatile("mma.sync.aligned.m16n8k16.row.col.f32.bf16.bf16.f32 "
        "{%0,%1,%2,%3}, {%4,%5,%6,%7}, {%8,%9}, {%0,%1,%2,%3};"
        : "+f"(d[0]), "+f"(d[1]), "+f"(d[2]), "+f"(d[3])
        : "r"(a[0]), "r"(a[1]), "r"(a[2]), "r"(a[3]), "r"(b0), "r"(b1));
}

#define CP16(d, s) \
    asm volatile("cp.async.ca.shared.global [%0], [%1], 16;" :: "r"(d), "l"(s) : "memory")
#define CP_COMMIT() asm volatile("cp.async.commit_group;" ::: "memory")
#define CP_WAIT0()  asm volatile("cp.async.wait_group 0;" ::: "memory")

// ===================== problem constants / scratch =====================
// B=8, H=W=256, C=192, WS=8, SHIFT=4, 6 heads x 32 dim; tokens (b, window, pixel)
#define NTOK 524288

__device__ __align__(16) float g_qkv[(size_t)NTOK * 576];
__device__ __align__(16) float g_att[(size_t)NTOK * 192];
// split weights, transposed to [n][k=192] bf16 row-major
__device__ __align__(16) __nv_bfloat16 g_wq_hi[576 * 192], g_wq_lo[576 * 192];
__device__ __align__(16) __nv_bfloat16 g_wo_hi[192 * 192], g_wo_lo[192 * 192];

// token -> image row; roll(-4) on input and roll(+4) on output are the same map
static __device__ __forceinline__ int src_row(int t) {
    int b   = t >> 16;
    int win = (t >> 6) & 1023;
    int p   = t & 63;
    int h = (((win >> 5) << 3) + (p >> 3) + 4) & 255;
    int w = (((win & 31) << 3) + (p & 7)  + 4) & 255;
    return (b << 16) | (h << 8) | w;
}

// =====================================================================
// Prep: split fp32 weight [k][N] into bf16 hi/lo, transposed to [n][192]
// =====================================================================
__global__ void k_conv_w(const float* __restrict__ w, int N, int sel) {
    int idx = blockIdx.x * 256 + threadIdx.x;
    if (idx >= 192 * N) return;
    int k = idx / N, n = idx % N;
    float hf, lf; bsplit(w[idx], hf, lf);
    __nv_bfloat16* hi = sel ? g_wo_hi : g_wq_hi;
    __nv_bfloat16* lo = sel ? g_wo_lo : g_wq_lo;
    hi[n * 192 + k] = __float2bfloat16(hf);
    lo[n * 192 + k] = __float2bfloat16(lf);
}

// =====================================================================
// Split-bf16 GEMM via mma.sync (HMMA). CTA: 128 thr / 4 warps.
// M-tile 128, K=192 resident (A hi/lo, row stride 400B -> conflict-free
// LDSM), N chunks of 64 double-buffered via cp.async.
// Warp tile 32x64. acc = Ahi*Bhi + Ahi*Blo + Alo*Bhi  (fp32 accum).
// SMEM: A_hi[0,51200) A_lo[51200,102400) B2bufs[102400, 204800)
//       per B buf: hi 25600, lo 25600 (rows stride 400B)
// =====================================================================
template<int NCHUNK, bool QKV>
__global__ void __launch_bounds__(128, 1)
k_gemm(const float* __restrict__ Aext, const float* __restrict__ bias,
       float* __restrict__ Oext)
{
    extern __shared__ char smem[];
    const u32 sb = smem_u32(smem);
    const int tid = threadIdx.x;
    const int t0 = blockIdx.x << 7;

    const float* Asrc = QKV ? Aext : g_att;
    float* Out        = QKV ? g_qkv : Oext;
    const int ostride = QKV ? 576 : 192;
    const __nv_bfloat16* whi = QKV ? g_wq_hi : g_wo_hi;
    const __nv_bfloat16* wlo = QKV ? g_wq_lo : g_wo_lo;

    // ---- prefetch B chunk via cp.async (row stride 384B -> 400B) ----
    auto prefetchB = [&](int c, int buf) {
        const char* srcH = (const char*)(whi + (size_t)c * 64 * 192);
        const char* srcL = (const char*)(wlo + (size_t)c * 64 * 192);
        u32 dst = sb + 102400 + (u32)buf * 51200;
        #pragma unroll
        for (int i = 0; i < 12; ++i) {
            int idx = tid + (i << 7);          // 0..1535
            int row = idx / 24, col = idx - row * 24;
            u32 off = row * 400 + (col << 4);
            int gof = row * 384 + (col << 4);
            CP16(dst + off,          srcH + gof);
            CP16(dst + 25600 + off,  srcL + gof);
        }
    };

    prefetchB(0, 0);
    CP_COMMIT();

    // ---- A tile: gather + split convert (thread = row) ----
    {
        size_t arow = QKV ? (size_t)src_row(t0 + tid) : (size_t)(t0 + tid);
        const float4* ar = (const float4*)(Asrc + arow * 192);
        char* hb = smem + tid * 400;
        char* lb = smem + 51200 + tid * 400;
        #pragma unroll
        for (int kk = 0; kk < 24; ++kk) {
            float4 f0 = ar[2 * kk], f1 = ar[2 * kk + 1];
            float h0,l0,h1,l1,h2,l2,h3,l3,h4,l4,h5,l5,h6,l6,h7,l7;
            bsplit(f0.x,h0,l0); bsplit(f0.y,h1,l1); bsplit(f0.z,h2,l2); bsplit(f0.w,h3,l3);
            bsplit(f1.x,h4,l4); bsplit(f1.y,h5,l5); bsplit(f1.z,h6,l6); bsplit(f1.w,h7,l7);
            *(uint4*)(hb + kk * 16) = make_uint4(bfp(h0,h1), bfp(h2,h3), bfp(h4,h5), bfp(h6,h7));
            *(uint4*)(lb + kk * 16) = make_uint4(bfp(l0,l1), bfp(l2,l3), bfp(l4,l5), bfp(l6,l7));
        }
    }

    CP_WAIT0();
    __syncthreads();

    // ---- ldmatrix lane addressing ----
    const int w = tid >> 5, lane = tid & 31;
    const int grp = lane >> 3, lr = lane & 7;
    const int mrow = w * 32 + ((grp & 1) << 3) + lr;
    const u32 kadd = (u32)((grp >> 1) << 4);            // 0 or 16 bytes
    const u32 aH0 = sb + (u32)mrow * 400 + kadd;        // mt=0 (mt=1: +6400)
    const u32 aL0 = aH0 + 51200;
    const u32 boff = (u32)((((grp & 1) << 3) + lr) * 400) + kadd;   // + ntp*6400

    const int qr = lane >> 2;            // C frag row-in-group
    const int qc = (lane & 3) << 1;      // C frag col pair

    for (int c = 0; c < NCHUNK; ++c) {
        const int buf = c & 1;
        if (c + 1 < NCHUNK) { prefetchB(c + 1, buf ^ 1); CP_COMMIT(); }

        float acc[16][4];
        #pragma unroll
        for (int i = 0; i < 16; ++i)
            #pragma unroll
            for (int j = 0; j < 4; ++j) acc[i][j] = 0.f;

        const u32 bB = sb + 102400 + (u32)buf * 51200 + boff;

        for (int s = 0; s < 12; ++s) {
            const u32 ko = (u32)s * 32;
            u32 ah[2][4], al[2][4];
            LDSM4(ah[0], aH0 + ko);        LDSM4(ah[1], aH0 + 6400 + ko);
            LDSM4(al[0], aL0 + ko);        LDSM4(al[1], aL0 + 6400 + ko);
            u32 bh[4][4], bl[4][4];
            #pragma unroll
            for (int t = 0; t < 4; ++t) {
                LDSM4(bh[t], bB + (u32)t * 6400 + ko);
                LDSM4(bl[t], bB + 25600 + (u32)t * 6400 + ko);
            }
            #pragma unroll
            for (int mt = 0; mt < 2; ++mt)
                #pragma unroll
                for (int t = 0; t < 4; ++t) {
                    float* d0 = acc[mt * 8 + 2 * t];
                    float* d1 = acc[mt * 8 + 2 * t + 1];
                    mma16816(d0, ah[mt], bh[t][0], bh[t][2]);   // hi*hi
                    mma16816(d0, ah[mt], bl[t][0], bl[t][2]);   // hi*lo
                    mma16816(d0, al[mt], bh[t][0], bh[t][2]);   // lo*hi
                    mma16816(d1, ah[mt], bh[t][1], bh[t][3]);
                    mma16816(d1, ah[mt], bl[t][1], bl[t][3]);
                    mma16816(d1, al[mt], bh[t][1], bh[t][3]);
                }
        }

        // ---- epilogue: bias + store (QKV -> scratch; OUT -> scatter) ----
        const int nb = c * 64;
        #pragma unroll
        for (int mt = 0; mt < 2; ++mt) {
            int r0 = w * 32 + mt * 16 + qr;
            int ta = t0 + r0, tb2 = ta + 8;
            size_t oa = (QKV ? (size_t)ta  : (size_t)src_row(ta))  * ostride;
            size_t ob = (QKV ? (size_t)tb2 : (size_t)src_row(tb2)) * ostride;
            #pragma unroll
            for (int t = 0; t < 8; ++t) {
                int n = nb + t * 8 + qc;
                float bx = bias[n], by = bias[n + 1];
                const float* d = acc[mt * 8 + t];
                *(float2*)(Out + oa + n) = make_float2(d[0] + bx, d[1] + by);
                *(float2*)(Out + ob + n) = make_float2(d[2] + bx, d[3] + by);
            }
        }

        if (c + 1 < NCHUNK) { CP_WAIT0(); __syncthreads(); }
    }
}

// =====================================================================
// Windowed attention: 128 threads = 2 heads x 64 query pixels (f32x2).
// =====================================================================
__global__ void __launch_bounds__(128) k_attn(const float* __restrict__ rel_pos)
{
    __shared__ ulonglong2 ks[2][64][8];
    __shared__ ulonglong2 vs[2][64][8];
    __shared__ float bs[2][225];

    const int tid  = threadIdx.x;
    const int hh   = tid >> 6;
    const int p    = tid & 63;
    const int wid  = blockIdx.x;                 // b*1024 + window
    const int head = (blockIdx.y << 1) | hh;
    const int wh = (wid >> 5) & 31, wwc = wid & 31;
    const size_t tb = (size_t)wid << 6;
    const float* base = g_qkv + tb * 576;

    #pragma unroll
    for (int l = 0; l < 8; ++l) {
        int flat = (l << 6) + p;
        int row = flat >> 3, c4 = flat & 7;
        const float* kr = base + row * 576 + 192 + head * 32;
        const float* vr = base + row * 576 + 384 + head * 32;
        ks[hh][row][c4] = ((const ulonglong2*)kr)[c4];
        vs[hh][row][c4] = ((const ulonglong2*)vr)[c4];
    }
    for (int i = p; i < 225; i += 64) bs[hh][i] = rel_pos[head * 225 + i];

    ulonglong2 q2[8];
    {
        const ulonglong2* qp = (const ulonglong2*)(base + p * 576 + head * 32);
        #pragma unroll
        for (int c = 0; c < 8; ++c) q2[c] = qp[c];
    }
    __syncthreads();

    const int pi = p >> 3, pj = p & 7;
    const bool lastH = (wh == 31), lastW = (wwc == 31);

    float s[64];
    #pragma unroll
    for (int q = 0; q < 64; ++q) {
        u64 a = 0ull;
        #pragma unroll
        for (int c = 0; c < 8; ++c) {
            ulonglong2 t = ks[hh][q][c];
            ffma2(a, q2[c].x, t.x);
            ffma2(a, q2[c].y, t.y);
        }
        float2 f = unpack2(a);
        int qi = q >> 3, qj = q & 7;
        float v = (f.x + f.y) * 0.17677669529663687f
                + bs[hh][(pi - qi + 7) * 15 + (pj - qj + 7)];
        bool m = (lastH && ((pi < 4) != (qi < 4))) ||
                 (lastW && ((pj < 4) != (qj < 4)));
        s[q] = m ? -1e30f : v;
    }

    float mx = -1e30f;
    #pragma unroll
    for (int q = 0; q < 64; ++q) mx = fmaxf(mx, s[q]);
    float sum = 0.f;
    #pragma unroll
    for (int q = 0; q < 64; ++q) { float e = __expf(s[q] - mx); s[q] = e; sum += e; }
    const float inv = 1.f / sum;

    u64 o[16];
    #pragma unroll
    for (int d = 0; d < 16; ++d) o[d] = 0ull;
    #pragma unroll
    for (int q = 0; q < 64; ++q) {
        float pr = s[q] * inv;
        u64 pd = pack2(pr, pr);
        #pragma unroll
        for (int d = 0; d < 8; ++d) {
            ulonglong2 t = vs[hh][q][d];
            ffma2(o[2*d],   pd, t.x);
            ffma2(o[2*d+1], pd, t.y);
        }
    }
    u64* op = (u64*)(g_att + (tb + p) * 192 + head * 32);
    #pragma unroll
    for (int d = 0; d < 16; ++d) op[d] = o[d];
}

// =====================================================================
extern "C" void kernel_launch(void* const* d_in, const int* in_sizes, int n_in,
                              void* d_out, int out_size)
{
    const float* x  = (const float*)d_in[0];   // (8,256,256,192) f32
    const float* wq = (const float*)d_in[1];   // (192,576)
    const float* bq = (const float*)d_in[2];   // (576,)
    const float* rp = (const float*)d_in[3];   // (6,15,15)
    const float* wo = (const float*)d_in[4];   // (192,192)
    const float* bo = (const float*)d_in[5];   // (192,)
    float* out = (float*)d_out;                // (8,256,256,192) f32

    const int SMEM_TOT = 204800;
    cudaFuncSetAttribute(k_gemm<9, true>,  cudaFuncAttributeMaxDynamicSharedMemorySize, SMEM_TOT);
    cudaFuncSetAttribute(k_gemm<3, false>, cudaFuncAttributeMaxDynamicSharedMemorySize, SMEM_TOT);

    k_conv_w<<<(192 * 576 + 255) / 256, 256>>>(wq, 576, 0);
    k_conv_w<<<(192 * 192 + 255) / 256, 256>>>(wo, 192, 1);

    k_gemm<9, true><<<4096, 128, SMEM_TOT>>>(x, bq, nullptr);     // QKV proj
    k_attn<<<dim3(8192, 3), 128>>>(rp);                           // attention
    k_gemm<3, false><<<4096, 128, SMEM_TOT>>>(nullptr, bo, out);  // out proj + scatter
}